// round 12
// baseline (speedup 1.0000x reference)
#include <cuda_runtime.h>

#define AR_P 64
#define AR_T 65536
#define HLEN 65536
#define NB   16          // persistent grid for kAB (few CTAs -> cheap barrier)
#define NT   512

__device__ __align__(16) float g_hpad[AR_P + HLEN];  // h with 64 leading zeros
__device__ __align__(16) float g_means[AR_T];        // bias * cumsum(h)
__device__ float g_part[NB];                         // per-segment sums
__device__ unsigned g_bar_count = 0;                 // returns to 0 every barrier
__device__ unsigned g_bar_gen   = 0;                 // monotonic, replay-safe

// ---------------------------------------------------------------------------
// Grid-wide barrier (gen-counter; NB co-resident CTAs, 16 arrivals -> ~430cyc).
// ---------------------------------------------------------------------------
__device__ __forceinline__ void grid_bar() {
    __threadfence();
    __syncthreads();
    if (threadIdx.x == 0) {
        const unsigned g = *((volatile unsigned*)&g_bar_gen);
        if (atomicAdd(&g_bar_count, 1u) == NB - 1u) {
            atomicExch(&g_bar_count, 0u);
            __threadfence();
            atomicAdd(&g_bar_gen, 1u);
        } else {
            while (*((volatile unsigned*)&g_bar_gen) == g) __nanosleep(64);
        }
        __threadfence();
    }
    __syncthreads();
}

// ---------------------------------------------------------------------------
// Conflict-free 64-tap convolution for 4 consecutive outputs (smem source).
// out[r] = sum_{i=0}^{63} src[base0 + r - i] * phi[i], r = 0..3.
// ---------------------------------------------------------------------------
__device__ __forceinline__ void conv4_f4(const float* __restrict__ src, int base0,
                                         const float* __restrict__ phi,
                                         float& a0, float& a1, float& a2, float& a3) {
    const float4 va = *reinterpret_cast<const float4*>(&src[base0]);
    const float4 vb = *reinterpret_cast<const float4*>(&src[base0 - 4]);
    float v0 = vb.x, v1 = vb.y, v2 = vb.z, v3 = vb.w;
    float v4 = va.x, v5 = va.y, v6 = va.z, v7 = va.w;
    a0 = 0.f; a1 = 0.f; a2 = 0.f; a3 = 0.f;
    #pragma unroll
    for (int i4 = 0; i4 < 16; i4++) {
        if (i4 > 0) {
            v4 = v0; v5 = v1; v6 = v2; v7 = v3;
            const float4 nv = *reinterpret_cast<const float4*>(&src[base0 - 4 - 4 * i4]);
            v0 = nv.x; v1 = nv.y; v2 = nv.z; v3 = nv.w;
        }
        const float4 p = *reinterpret_cast<const float4*>(&phi[4 * i4]);
        a0 += v4 * p.x; a1 += v5 * p.x; a2 += v6 * p.x; a3 += v7 * p.x;
        a0 += v3 * p.y; a1 += v4 * p.y; a2 += v5 * p.y; a3 += v6 * p.y;
        a0 += v2 * p.z; a1 += v3 * p.z; a2 += v4 * p.z; a3 += v5 * p.z;
        a0 += v1 * p.w; a1 += v2 * p.w; a2 += v3 * p.w; a3 += v4 * p.w;
    }
}

// 4-way-split 64-tap dot: returns sum_j A[abase + j] * B[btop - j]
__device__ __forceinline__ float dot64_4acc_fwd_rev(const float* __restrict__ A, int abase,
                                                    const float* __restrict__ B, int btop) {
    float s0 = 0.f, s1 = 0.f, s2 = 0.f, s3 = 0.f;
    #pragma unroll
    for (int j = 0; j < AR_P; j += 4) {
        s0 += A[abase + j + 0] * B[btop - j - 0];
        s1 += A[abase + j + 1] * B[btop - j - 1];
        s2 += A[abase + j + 2] * B[btop - j - 2];
        s3 += A[abase + j + 3] * B[btop - j - 3];
    }
    return (s0 + s1) + (s2 + s3);
}

// ---------------------------------------------------------------------------
// kAB: persistent 16-block kernel.
//   phase A (block 0): h[0..2048) in smem, publish to global.
//   phase B (all):     doubling levels 2048 -> 65536, smem-staged windows.
//   phase C (all):     segmented prefix sum -> g_means = bias * cumsum(h).
// ---------------------------------------------------------------------------
__global__ __launch_bounds__(NT) void kAB(const float* __restrict__ params,
                                          const float* __restrict__ bias) {
    __shared__ __align__(16) float Pp[2 * AR_P];        // params + 64 zeros
    __shared__ __align__(16) float hs[AR_P + 2048];     // block-0 staging
    __shared__ __align__(16) float phi[AR_P];
    __shared__ __align__(16) float tailh[AR_P];
    __shared__ __align__(16) float hw[2048 + AR_P];     // max chunk + halo
    __shared__ float wsum[NT / 32];
    __shared__ float pscan[NB];

    const int tid = threadIdx.x;
    const int lane = tid & 31;
    const int wid = tid >> 5;
    const int blk = blockIdx.x;

    if (tid < 2 * AR_P) Pp[tid] = (tid < AR_P) ? params[tid] : 0.0f;
    __syncthreads();

    // ================= phase A : block 0 only =================
    if (blk == 0) {
        if (tid < AR_P) hs[tid] = 0.0f;      // left zero pad h_{-64..-1}
        __syncthreads();

        // bootstrap h_0..h_7 on thread 0 (~30 serial FMA)
        if (tid == 0) {
            float h[8];
            h[0] = 1.0f;
            #pragma unroll
            for (int m = 1; m < 8; m++) {
                float acc = 0.0f;
                #pragma unroll
                for (int k = 0; k < 7; k++)
                    if (k < m) acc += Pp[k] * h[m - 1 - k];
                h[m] = acc;
            }
            #pragma unroll
            for (int m = 0; m < 8; m++) hs[AR_P + m] = h[m];
        }
        __syncthreads();

        // levels n = 8..32 : scalar, warp 0 only
        if (tid < 32) {
            for (int n = 8; n < AR_P; n <<= 1) {
                #pragma unroll 2
                for (int i = lane; i < AR_P; i += 32)
                    phi[i] = dot64_4acc_fwd_rev(Pp, i, hs, AR_P + n - 1);
                __syncwarp();
                if (lane < n)
                    hs[AR_P + n + lane] = dot64_4acc_fwd_rev(phi, 0, hs, AR_P + lane);
                __syncwarp();
            }
            // levels n = 64, 128 : float4 path, still warp 0
            for (int n = AR_P; n < 256; n <<= 1) {
                #pragma unroll 2
                for (int i = lane; i < AR_P; i += 32)
                    phi[i] = dot64_4acc_fwd_rev(Pp, i, hs, AR_P + n - 1);
                __syncwarp();
                const int nt4 = n >> 2;
                for (int t = lane; t < nt4; t += 32) {
                    float a0, a1, a2, a3;
                    conv4_f4(hs, AR_P + 4 * t, phi, a0, a1, a2, a3);
                    *reinterpret_cast<float4*>(&hs[AR_P + n + 4 * t]) =
                        make_float4(a0, a1, a2, a3);
                }
                __syncwarp();
            }
        }
        __syncthreads();

        // levels n = 256, 512, 1024 : full block, smem
        for (int n = 256; n < 2048; n <<= 1) {
            if (tid < AR_P)
                phi[tid] = dot64_4acc_fwd_rev(Pp, tid, hs, AR_P + n - 1);
            __syncthreads();
            const int nt4 = n >> 2;
            if (tid < nt4) {
                float a0, a1, a2, a3;
                conv4_f4(hs, AR_P + 4 * tid, phi, a0, a1, a2, a3);
                *reinterpret_cast<float4*>(&hs[AR_P + n + 4 * tid]) =
                    make_float4(a0, a1, a2, a3);
            }
            __syncthreads();
        }

        // publish pad + h[0..2048)
        const float4* s4 = reinterpret_cast<const float4*>(hs);
        float4* d4 = reinterpret_cast<float4*>(g_hpad);
        for (int q = tid; q < (AR_P + 2048) / 4; q += NT) d4[q] = s4[q];
    }
    grid_bar();   // h[0..2048) visible chip-wide

    // ================= phase B : distributed doubling, smem-staged =================
    #pragma unroll
    for (int N = 2048; N < HLEN; N <<= 1) {
        const int chunk = N / NB;                 // 128..2048 floats per block
        const int base = blk * chunk;             // output offset within [0, N)

        // stage window h[base-64 .. base+chunk): g_hpad[base + q] (pad = 64)
        for (int q = tid; q < (chunk + AR_P) / 4; q += NT)
            reinterpret_cast<float4*>(hw)[q] =
                reinterpret_cast<const float4*>(&g_hpad[base])[q];
        // stage tail h[N-64..N) = g_hpad[N .. N+64)
        if (tid < AR_P / 4)
            reinterpret_cast<float4*>(tailh)[tid] =
                reinterpret_cast<const float4*>(&g_hpad[N])[tid];
        __syncthreads();
        if (tid < AR_P)
            phi[tid] = dot64_4acc_fwd_rev(Pp, tid, tailh, AR_P - 1);
        __syncthreads();

        if (tid < chunk / 4) {
            float a0, a1, a2, a3;
            conv4_f4(hw, AR_P + 4 * tid, phi, a0, a1, a2, a3);
            *reinterpret_cast<float4*>(&g_hpad[AR_P + N + base + 4 * tid]) =
                make_float4(a0, a1, a2, a3);
        }
        grid_bar();
    }

    // ================= phase C : prefix sum -> means =================
    const float bv = bias[0];
    const int seg = blk * (HLEN / NB);            // 4096 elems per block
    const int e0 = seg + tid * 8;
    const float4 x0 = *reinterpret_cast<const float4*>(&g_hpad[AR_P + e0]);
    const float4 x1 = *reinterpret_cast<const float4*>(&g_hpad[AR_P + e0 + 4]);
    const float tsum = ((x0.x + x0.y) + (x0.z + x0.w)) +
                       ((x1.x + x1.y) + (x1.z + x1.w));

    float inc = tsum;
    #pragma unroll
    for (int o = 1; o < 32; o <<= 1) {
        const float t = __shfl_up_sync(0xffffffffu, inc, o);
        if (lane >= o) inc += t;
    }
    if (lane == 31) wsum[wid] = inc;
    __syncthreads();
    float wbase = 0.f, btot = 0.f;
    #pragma unroll
    for (int w = 0; w < NT / 32; w++) {
        const float t = wsum[w];
        wbase += (w < wid) ? t : 0.f;
        btot += t;
    }
    if (tid == 0) g_part[blk] = btot;
    grid_bar();

    // scan the 16 segment partials on warp 0
    if (tid < 32) {
        float p = (lane < NB) ? g_part[lane] : 0.0f;
        #pragma unroll
        for (int o = 1; o < 32; o <<= 1) {
            const float t = __shfl_up_sync(0xffffffffu, p, o);
            if (lane >= o) p += t;
        }
        if (lane < NB) pscan[lane] = p;
    }
    __syncthreads();

    const float segbase = (blk > 0) ? pscan[blk - 1] : 0.0f;
    float run = segbase + wbase + (inc - tsum);
    float4 m0, m1;
    run += x0.x; m0.x = bv * run;
    run += x0.y; m0.y = bv * run;
    run += x0.z; m0.z = bv * run;
    run += x0.w; m0.w = bv * run;
    run += x1.x; m1.x = bv * run;
    run += x1.y; m1.y = bv * run;
    run += x1.z; m1.z = bv * run;
    run += x1.w; m1.w = bv * run;
    *reinterpret_cast<float4*>(&g_means[e0]) = m0;
    *reinterpret_cast<float4*>(&g_means[e0 + 4]) = m1;
}

// ---------------------------------------------------------------------------
// k3: out[b,t] = means[t] + 0.3*noise[b,t]  (float4 streaming)
// ---------------------------------------------------------------------------
__global__ __launch_bounds__(256) void k3_out(const float4* __restrict__ noise,
                                              float4* __restrict__ out) {
    const int idx = blockIdx.x * 256 + threadIdx.x;
    const int t4 = idx & (AR_T / 4 - 1);
    const float4 nz = __ldcs(&noise[idx]);                           // stream
    const float4 mn = reinterpret_cast<const float4*>(g_means)[t4];  // L2-resident
    float4 r;
    r.x = fmaf(0.3f, nz.x, mn.x);
    r.y = fmaf(0.3f, nz.y, mn.y);
    r.z = fmaf(0.3f, nz.z, mn.z);
    r.w = fmaf(0.3f, nz.w, mn.w);
    __stcs(&out[idx], r);                                            // evict-first
}

extern "C" void kernel_launch(void* const* d_in, const int* in_sizes, int n_in,
                              void* d_out, int out_size) {
    // identify inputs by element count (params=64, bias=1, noise=256*65536)
    const float* params = nullptr;
    const float* bias   = nullptr;
    const float* noise  = nullptr;
    for (int i = 0; i < n_in; i++) {
        if (in_sizes[i] == AR_P)      params = (const float*)d_in[i];
        else if (in_sizes[i] == 1)    bias   = (const float*)d_in[i];
        else                          noise  = (const float*)d_in[i];
    }

    kAB<<<NB, NT>>>(params, bias);

    const int total4 = out_size / 4;          // 4,194,304 float4s
    k3_out<<<total4 / 256, 256>>>((const float4*)noise, (float4*)d_out);
}

// round 15
// speedup vs baseline: 1.1708x; 1.1708x over previous
#include <cuda_runtime.h>

#define AR_P 64
#define AR_T 65536
#define CHUNK_L 8192
#define N_CHUNKS 8   // AR_T / CHUNK_L

__device__ __align__(16) float g_hpad[AR_P + CHUNK_L];   // h with 64 leading zeros
__device__ __align__(16) float g_H[CHUNK_L];             // inclusive prefix sum of h
__device__ float g_phi[N_CHUNKS][AR_P];                  // per-chunk boundary projections
__device__ __align__(16) float g_means[AR_T];

// ---------------------------------------------------------------------------
// Conflict-free 64-tap convolution for 4 consecutive outputs (smem source).
// out[r] = sum_{i=0}^{63} src[base0 + r - i] * phi[i], r = 0..3.
// ---------------------------------------------------------------------------
__device__ __forceinline__ void conv4_f4(const float* __restrict__ src, int base0,
                                         const float* __restrict__ phi,
                                         float& a0, float& a1, float& a2, float& a3) {
    const float4 va = *reinterpret_cast<const float4*>(&src[base0]);
    const float4 vb = *reinterpret_cast<const float4*>(&src[base0 - 4]);
    float v0 = vb.x, v1 = vb.y, v2 = vb.z, v3 = vb.w;
    float v4 = va.x, v5 = va.y, v6 = va.z, v7 = va.w;
    a0 = 0.f; a1 = 0.f; a2 = 0.f; a3 = 0.f;
    #pragma unroll
    for (int i4 = 0; i4 < 16; i4++) {
        if (i4 > 0) {
            v4 = v0; v5 = v1; v6 = v2; v7 = v3;
            const float4 nv = *reinterpret_cast<const float4*>(&src[base0 - 4 - 4 * i4]);
            v0 = nv.x; v1 = nv.y; v2 = nv.z; v3 = nv.w;
        }
        const float4 p = *reinterpret_cast<const float4*>(&phi[4 * i4]);
        a0 += v4 * p.x; a1 += v5 * p.x; a2 += v6 * p.x; a3 += v7 * p.x;
        a0 += v3 * p.y; a1 += v4 * p.y; a2 += v5 * p.y; a3 += v6 * p.y;
        a0 += v2 * p.z; a1 += v3 * p.z; a2 += v4 * p.z; a3 += v5 * p.z;
        a0 += v1 * p.w; a1 += v2 * p.w; a2 += v3 * p.w; a3 += v4 * p.w;
    }
}

// returns sum_{j=0..63} A[abase + j] * B[btop - j]
__device__ __forceinline__ float dot64_4acc_fwd_rev(const float* __restrict__ A, int abase,
                                                    const float* __restrict__ B, int btop) {
    float s0 = 0.f, s1 = 0.f, s2 = 0.f, s3 = 0.f;
    #pragma unroll
    for (int j = 0; j < AR_P; j += 4) {
        s0 += A[abase + j + 0] * B[btop - j - 0];
        s1 += A[abase + j + 1] * B[btop - j - 1];
        s2 += A[abase + j + 2] * B[btop - j - 2];
        s3 += A[abase + j + 3] * B[btop - j - 3];
    }
    return (s0 + s1) + (s2 + s3);
}

// returns sum_{j=0..63} A[j] * B[j]   (both forward)
__device__ __forceinline__ float dot64_4acc_fwd_fwd(const float* __restrict__ A,
                                                    const float* __restrict__ B) {
    float s0 = 0.f, s1 = 0.f, s2 = 0.f, s3 = 0.f;
    #pragma unroll
    for (int j = 0; j < AR_P; j += 4) {
        s0 += A[j + 0] * B[j + 0];
        s1 += A[j + 1] * B[j + 1];
        s2 += A[j + 2] * B[j + 2];
        s3 += A[j + 3] * B[j + 3];
    }
    return (s0 + s1) + (s2 + s3);
}

// ---------------------------------------------------------------------------
// Kernel 1 (single block, 1024 thr):
//   h by wavefront + doubling (to 8192+64), prefix sum -> g_H,
//   Hankel-matvec boundary hop  s_{c+1}[j] = sum_{j'} h[L-j+j'] s_c[j'] + bv*H[L-1-j],
//   then ALL phi_c in parallel:  phi_c[i] = sum_j Pp[i+j] s_c[j].
// ---------------------------------------------------------------------------
__global__ __launch_bounds__(1024) void k1_prep(const float* __restrict__ params,
                                                const float* __restrict__ bias) {
    __shared__ __align__(16) float Pp[2 * AR_P];                    // params + 64 zeros
    __shared__ __align__(16) float hs[AR_P + CHUNK_L + AR_P];       // pad + h[0..8256)
    __shared__ __align__(16) float phi[AR_P];
    __shared__ float red[32];
    __shared__ float Htail[AR_P];                                   // H[8191-j]
    __shared__ float scur[AR_P];                                    // current state
    __shared__ float sst[N_CHUNKS][AR_P];                           // all states

    const int tid = threadIdx.x;
    const int lane = tid & 31;
    const float bv = bias[0];

    if (tid < 2 * AR_P) Pp[tid] = (tid < AR_P) ? params[tid] : 0.0f;
    if (tid < AR_P) hs[tid] = 0.0f;          // left zero pad h_{-64..-1}
    __syncthreads();

    // ---- wavefront: h[0..32) in warp 0 (serial chain via shfl) ----
    if (tid < 32) {
        float val = (lane == 0) ? 1.0f : 0.0f;   // h_0 = 1
        float acc = 0.0f;
        #pragma unroll
        for (int r = 0; r < 31; r++) {
            const float hr = __shfl_sync(0xffffffffu, val, r);   // h_r (final)
            if (lane > r) acc = fmaf(Pp[lane - 1 - r], hr, acc);
            if (lane == r + 1) val = acc;                        // h_{r+1} done
        }
        hs[AR_P + lane] = val;
        __syncwarp();

        // ---- level n = 32 : scalar, warp 0 ----
        {
            const int n = 32;
            #pragma unroll 2
            for (int i = lane; i < AR_P; i += 32)
                phi[i] = dot64_4acc_fwd_rev(Pp, i, hs, AR_P + n - 1);
            __syncwarp();
            hs[AR_P + n + lane] = dot64_4acc_fwd_rev(phi, 0, hs, AR_P + lane);
            __syncwarp();
        }

        // ---- levels n = 64, 128 : float4 path, still warp 0 ----
        for (int n = AR_P; n < 256; n <<= 1) {
            #pragma unroll 2
            for (int i = lane; i < AR_P; i += 32)
                phi[i] = dot64_4acc_fwd_rev(Pp, i, hs, AR_P + n - 1);
            __syncwarp();
            const int nt = n >> 2;
            for (int t = lane; t < nt; t += 32) {
                float a0, a1, a2, a3;
                conv4_f4(hs, AR_P + 4 * t, phi, a0, a1, a2, a3);
                *reinterpret_cast<float4*>(&hs[AR_P + n + 4 * t]) =
                    make_float4(a0, a1, a2, a3);
            }
            __syncwarp();
        }
    }
    __syncthreads();

    // ---- levels n = 256 .. 4096 : full block ----
    for (int n = 256; n < CHUNK_L; n <<= 1) {
        if (tid < AR_P)
            phi[tid] = dot64_4acc_fwd_rev(Pp, tid, hs, AR_P + n - 1);
        __syncthreads();
        const int nt = n >> 2;
        if (tid < nt) {
            float a0, a1, a2, a3;
            conv4_f4(hs, AR_P + 4 * tid, phi, a0, a1, a2, a3);
            *reinterpret_cast<float4*>(&hs[AR_P + n + 4 * tid]) =
                make_float4(a0, a1, a2, a3);
        }
        __syncthreads();
    }

    // ---- extension: h[8192 .. 8256) (needed by the Hankel hop) ----
    if (tid < AR_P)
        phi[tid] = dot64_4acc_fwd_rev(Pp, tid, hs, AR_P + CHUNK_L - 1);
    __syncthreads();
    if (tid < AR_P)
        hs[AR_P + CHUNK_L + tid] = dot64_4acc_fwd_rev(phi, 0, hs, AR_P + tid);
    __syncthreads();

    // ---- write padded h[−64..8192) to global (float4) ----
    {
        const float4* s4 = reinterpret_cast<const float4*>(hs);
        float4* d4 = reinterpret_cast<float4*>(g_hpad);
        for (int q = tid; q < (AR_P + CHUNK_L) / 4; q += 1024) d4[q] = s4[q];
    }

    // ---- inclusive prefix sum of h -> g_H (8 elems/thread); stage H tail ----
    float v[8];
    float s = 0.0f;
    #pragma unroll
    for (int k = 0; k < 8; k++) { v[k] = hs[AR_P + tid * 8 + k]; s += v[k]; }
    float ss = s;
    #pragma unroll
    for (int o = 1; o < 32; o <<= 1) {
        const float t2 = __shfl_up_sync(0xffffffffu, ss, o);
        if (lane >= o) ss += t2;
    }
    if (lane == 31) red[tid >> 5] = ss;
    __syncthreads();
    if (tid < 32) {
        float ws = red[tid];
        #pragma unroll
        for (int o = 1; o < 32; o <<= 1) {
            const float t2 = __shfl_up_sync(0xffffffffu, ws, o);
            if (tid >= o) ws += t2;
        }
        red[tid] = ws;
    }
    __syncthreads();
    float run = (ss - s) + ((tid >= 32) ? red[(tid >> 5) - 1] : 0.0f);
    #pragma unroll
    for (int k = 0; k < 8; k++) {
        run += v[k];
        const int idx = tid * 8 + k;
        g_H[idx] = run;
        if (idx >= CHUNK_L - AR_P) Htail[CHUNK_L - 1 - idx] = run;  // H[8191-j]
    }

    // ---- Hankel hop: s_{c+1}[j] = sum_{j'} h[L-j+j'] s_c[j'] + bv*H[L-1-j] ----
    if (tid < AR_P) { scur[tid] = 0.0f; sst[0][tid] = 0.0f; }       // s_0 = 0
    __syncthreads();
    for (int c = 1; c < N_CHUNKS; c++) {
        float ns = 0.0f;
        if (tid < AR_P)
            ns = dot64_4acc_fwd_fwd(scur, &hs[AR_P + CHUNK_L - tid]) + bv * Htail[tid];
        __syncthreads();                      // all reads of scur complete
        if (tid < AR_P) { scur[tid] = ns; sst[c][tid] = ns; }
        __syncthreads();
    }

    // ---- ALL phi_c in parallel: phi_c[i] = sum_j Pp[i+j] * sst[c][j] ----
    if (tid < N_CHUNKS * AR_P) {
        const int c = tid >> 6;
        const int i = tid & (AR_P - 1);
        g_phi[c][i] = (c == 0) ? 0.0f : dot64_4acc_fwd_fwd(&Pp[i], sst[c]);
    }
}

// ---------------------------------------------------------------------------
// Kernel 2: fill all means. grid = 64 blocks x 256 threads.
// ---------------------------------------------------------------------------
__global__ __launch_bounds__(256) void k2_means(const float* __restrict__ bias) {
    const int c = blockIdx.x >> 3;
    const int part = blockIdx.x & 7;
    const int m0base = part * 1024;

    __shared__ __align__(16) float phi[AR_P];
    __shared__ __align__(16) float hw[1088];   // h_{m0base-64 .. m0base+1023}

    const int tid = threadIdx.x;
    if (tid < AR_P) phi[tid] = g_phi[c][tid];
    {
        const float4* g4 = reinterpret_cast<const float4*>(&g_hpad[m0base]);
        float4* s4 = reinterpret_cast<float4*>(hw);
        for (int q = tid; q < 1088 / 4; q += 256) s4[q] = g4[q];
    }
    __syncthreads();

    const float bv = bias[0];
    const int d = tid * 4;
    float a0, a1, a2, a3;
    conv4_f4(hw, 64 + d, phi, a0, a1, a2, a3);

    const int m = m0base + d;
    const float4 Hv = *reinterpret_cast<const float4*>(&g_H[m]);
    float4 r;
    r.x = fmaf(bv, Hv.x, a0);
    r.y = fmaf(bv, Hv.y, a1);
    r.z = fmaf(bv, Hv.z, a2);
    r.w = fmaf(bv, Hv.w, a3);
    *reinterpret_cast<float4*>(&g_means[c * CHUNK_L + m]) = r;
}

// ---------------------------------------------------------------------------
// Kernel 3: out[b,t] = means[t] + 0.3*noise[b,t]  (float4 streaming)
// ---------------------------------------------------------------------------
__global__ __launch_bounds__(256) void k3_out(const float4* __restrict__ noise,
                                              float4* __restrict__ out) {
    const int idx = blockIdx.x * 256 + threadIdx.x;
    const int t4 = idx & (AR_T / 4 - 1);
    const float4 nz = __ldcs(&noise[idx]);                           // stream
    const float4 mn = reinterpret_cast<const float4*>(g_means)[t4];  // L2-resident
    float4 r;
    r.x = fmaf(0.3f, nz.x, mn.x);
    r.y = fmaf(0.3f, nz.y, mn.y);
    r.z = fmaf(0.3f, nz.z, mn.z);
    r.w = fmaf(0.3f, nz.w, mn.w);
    __stcs(&out[idx], r);                                            // evict-first
}

extern "C" void kernel_launch(void* const* d_in, const int* in_sizes, int n_in,
                              void* d_out, int out_size) {
    // identify inputs by element count (params=64, bias=1, noise=256*65536)
    const float* params = nullptr;
    const float* bias   = nullptr;
    const float* noise  = nullptr;
    for (int i = 0; i < n_in; i++) {
        if (in_sizes[i] == AR_P)      params = (const float*)d_in[i];
        else if (in_sizes[i] == 1)    bias   = (const float*)d_in[i];
        else                          noise  = (const float*)d_in[i];
    }

    k1_prep<<<1, 1024>>>(params, bias);
    k2_means<<<N_CHUNKS * 8, 256>>>(bias);

    const int total4 = out_size / 4;          // 4,194,304 float4s
    k3_out<<<total4 / 256, 256>>>((const float4*)noise, (float4*)d_out);
}